// round 2
// baseline (speedup 1.0000x reference)
#include <cuda_runtime.h>
#include <cstdint>
#include <cstddef>

// Problem constants (fixed by the dataset)
static constexpr int ZDIM = 512;
static constexpr int MSZ  = 100;      // 10x10
static constexpr int MD   = 10;

// ---------------- scratch: lie_alg [B,100] ----------------
static constexpr int B_MAX = 131072;
__device__ float g_lie[(size_t)B_MAX * MSZ];   // 52.4 MB static scratch (no cudaMalloc)

// ---------------- Kernel A: lie_alg = z @ basis ----------------
// M-tile 256 batch rows per CTA, 256 threads.
// Thread (p = tid>>1, h = tid&1) computes half-rows h*5..h*5+4 (50 outputs = 25 f32x2)
// of matrices q0 = 2p and q1 = 2p+1 (register-reuse of each basis LDS across 2 matrices).
static constexpr int KC      = 64;    // K chunk
static constexpr int MATS_A  = 256;   // matrices per CTA
static constexpr int ZS_STR  = 65;    // padded z-tile row stride (floats), odd -> conflict-free
static constexpr int BS_STR  = 102;   // padded basis row stride (floats), even -> f32x2 aligned
static constexpr int SMEM_A_FLOATS = MATS_A * ZS_STR + KC * BS_STR;  // 16640 + 6528
static constexpr int SMEM_A_BYTES  = SMEM_A_FLOATS * 4;             // 92672 B

__device__ __forceinline__ void fma2(unsigned long long& d, unsigned long long a, unsigned long long b) {
    asm("fma.rn.f32x2 %0, %1, %2, %0;" : "+l"(d) : "l"(a), "l"(b));
}
__device__ __forceinline__ unsigned long long pack2(float v) {
    unsigned long long r;
    asm("mov.b64 %0, {%1, %1};" : "=l"(r) : "f"(v));
    return r;
}

extern "C" __global__ void __launch_bounds__(256)
lie_gemm_kernel(const float* __restrict__ z, const float* __restrict__ basis, int B)
{
    extern __shared__ float smem[];
    float* zs = smem;                       // [256][65]
    float* bs = smem + MATS_A * ZS_STR;     // [64][102]

    const int tid = threadIdx.x;
    const int h   = tid & 1;
    const int p   = tid >> 1;
    const int q0  = 2 * p;
    const int q1  = 2 * p + 1;
    const long long b0 = (long long)blockIdx.x * MATS_A;

    unsigned long long acc0[25];
    unsigned long long acc1[25];
#pragma unroll
    for (int e = 0; e < 25; e++) { acc0[e] = 0ull; acc1[e] = 0ull; }

    for (int kc = 0; kc < ZDIM; kc += KC) {
        // --- load basis chunk [KC][100] (contiguous 6400 floats), coalesced ---
        for (int i = tid; i < KC * MSZ; i += 256) {
            int r = i / MSZ, c = i - r * MSZ;
            bs[r * BS_STR + c] = basis[(size_t)(kc + r) * MSZ + c];
        }
        // --- load z tile [256][64] as float4, coalesced ---
        for (int i = tid; i < MATS_A * (KC / 4); i += 256) {
            int r  = i >> 4;           // KC/4 = 16
            int c4 = i & 15;
            float4 v = *reinterpret_cast<const float4*>(z + (size_t)(b0 + r) * ZDIM + kc + c4 * 4);
            float* dst = zs + r * ZS_STR + c4 * 4;
            dst[0] = v.x; dst[1] = v.y; dst[2] = v.z; dst[3] = v.w;
        }
        __syncthreads();

        const float* zp0 = zs + q0 * ZS_STR;
        const float* zp1 = zs + q1 * ZS_STR;
        const unsigned long long* bbase =
            reinterpret_cast<const unsigned long long*>(bs + h * 50);  // + k*(BS_STR/2)

#pragma unroll 2
        for (int k = 0; k < KC; k++) {
            unsigned long long zz0 = pack2(zp0[k]);
            unsigned long long zz1 = pack2(zp1[k]);
            const unsigned long long* br = bbase + (size_t)k * (BS_STR / 2);
#pragma unroll
            for (int e = 0; e < 25; e++) {
                unsigned long long bb = br[e];
                fma2(acc0[e], zz0, bb);
                fma2(acc1[e], zz1, bb);
            }
        }
        __syncthreads();
    }

    // --- epilogue: store packed pairs straight to scratch (STG.64) ---
    {
        size_t g0 = ((size_t)(b0 + q0) * MSZ + h * 50) >> 1;  // even offsets
        size_t g1 = ((size_t)(b0 + q1) * MSZ + h * 50) >> 1;
        unsigned long long* gq = reinterpret_cast<unsigned long long*>(g_lie);
#pragma unroll
        for (int e = 0; e < 25; e++) gq[g0 + e] = acc0[e];
#pragma unroll
        for (int e = 0; e < 25; e++) gq[g1 + e] = acc1[e];
    }
}

// ---------------- Kernel B: out = expm(lie_alg), degree-6 Taylor (Paterson-Stockmeyer) ----------------
// E = I + A + A^2/2 + A^3/6 + A^3 * (A/24 + A^2/120 + A^3/720)
// 256 threads, 128 matrices/CTA; thread (m = tid>>1, h = tid&1) owns rows h*5..h*5+4.
static constexpr int MATS_B = 128;
static constexpr int MB_STR = 101;   // padded row stride (floats): 101 % 32 = 5, gcd(5,32)=1
static constexpr int SMEM_B_BYTES = 3 * MATS_B * MB_STR * 4;  // 155,136 B

extern "C" __global__ void __launch_bounds__(256)
lie_expm_kernel(float* __restrict__ out, int B)
{
    extern __shared__ float smem[];
    float* sA = smem;                          // A, later W
    float* sB = sA + MATS_B * MB_STR;          // A^2, later U, later E
    float* sC = sB + MATS_B * MB_STR;          // A^3

    const int tid = threadIdx.x;
    const int h   = tid & 1;
    const int m   = tid >> 1;                  // local matrix 0..127
    const size_t blk_base = (size_t)blockIdx.x * MATS_B * MSZ;

    // load A (contiguous 12800 floats), coalesced
    for (int i = tid; i < MATS_B * MSZ; i += 256) {
        int r = i / MSZ, c = i - r * MSZ;
        sA[r * MB_STR + c] = g_lie[blk_base + i];
    }
    __syncthreads();

    const int mb = m * MB_STR;
    const int i0 = h * 5;

    // A^2 -> sB
    for (int i = i0; i < i0 + 5; i++) {
        float r[MD];
#pragma unroll
        for (int k = 0; k < MD; k++) r[k] = sA[mb + i * MD + k];
#pragma unroll
        for (int j = 0; j < MD; j++) {
            float s = 0.f;
#pragma unroll
            for (int k = 0; k < MD; k++) s += r[k] * sA[mb + k * MD + j];
            sB[mb + i * MD + j] = s;
        }
    }
    __syncthreads();

    // A^3 = A^2 * A -> sC
    for (int i = i0; i < i0 + 5; i++) {
        float r[MD];
#pragma unroll
        for (int k = 0; k < MD; k++) r[k] = sB[mb + i * MD + k];
#pragma unroll
        for (int j = 0; j < MD; j++) {
            float s = 0.f;
#pragma unroll
            for (int k = 0; k < MD; k++) s += r[k] * sA[mb + k * MD + j];
            sC[mb + i * MD + j] = s;
        }
    }
    __syncthreads();

    // elementwise: W = A/24 + A2/120 + A3/720 -> sA ;  U = I + A + A2/2 + A3/6 -> sB
    {
        const float c2 = 0.5f, c3 = 1.f / 6.f, c4 = 1.f / 24.f, c5 = 1.f / 120.f, c6 = 1.f / 720.f;
        for (int i = i0; i < i0 + 5; i++) {
#pragma unroll
            for (int j = 0; j < MD; j++) {
                int x = mb + i * MD + j;
                float a = sA[x], b2 = sB[x], a3 = sC[x];
                float w = a * c4 + b2 * c5 + a3 * c6;
                float u = (i == j ? 1.f : 0.f) + a + b2 * c2 + a3 * c3;
                sA[x] = w;
                sB[x] = u;
            }
        }
    }
    __syncthreads();

    // E = U + A^3 * W  -> sB (each thread touches only its own elements of sB)
    for (int i = i0; i < i0 + 5; i++) {
        float rc[MD];
#pragma unroll
        for (int k = 0; k < MD; k++) rc[k] = sC[mb + i * MD + k];
#pragma unroll
        for (int j = 0; j < MD; j++) {
            float s = sB[mb + i * MD + j];
#pragma unroll
            for (int k = 0; k < MD; k++) s += rc[k] * sA[mb + k * MD + j];
            sB[mb + i * MD + j] = s;
        }
    }
    __syncthreads();

    // coalesced store to output
    for (int i = tid; i < MATS_B * MSZ; i += 256) {
        int r = i / MSZ, c = i - r * MSZ;
        out[blk_base + i] = sB[r * MB_STR + c];
    }
}

// ---------------- launch ----------------
extern "C" void kernel_launch(void* const* d_in, const int* in_sizes, int n_in,
                              void* d_out, int out_size)
{
    const float* z     = (const float*)d_in[0];   // [B, 512]
    const float* basis = (const float*)d_in[1];   // [512, 10, 10]
    float* out = (float*)d_out;                   // [B, 10, 10]

    int B = in_sizes[0] / ZDIM;
    if (B > B_MAX) B = B_MAX;

    static bool attr_done = false;  // attribute setting is idempotent device config, not work
    if (!attr_done) {
        cudaFuncSetAttribute(lie_gemm_kernel, cudaFuncAttributeMaxDynamicSharedMemorySize, SMEM_A_BYTES);
        cudaFuncSetAttribute(lie_expm_kernel, cudaFuncAttributeMaxDynamicSharedMemorySize, SMEM_B_BYTES);
        attr_done = true;
    }

    int gridA = B / MATS_A;   // 512
    int gridB = B / MATS_B;   // 1024
    lie_gemm_kernel<<<gridA, 256, SMEM_A_BYTES>>>(z, basis, B);
    lie_expm_kernel<<<gridB, 256, SMEM_B_BYTES>>>(out, B);
}

// round 5
// speedup vs baseline: 1.5278x; 1.5278x over previous
#include <cuda_runtime.h>
#include <cuda_bf16.h>
#include <cstdint>
#include <cstddef>

#define DI __device__ __forceinline__
typedef unsigned long long ull;

static constexpr int ZDIM = 512;
static constexpr int MSZ  = 100;
static constexpr int NT   = 13;                   // n8 tiles (104 >= 100)
static constexpr int ASM_BYTES = 8 * NT * 32 * 16; // B-stage: [8 k16][13 nt][32 lanes] uint4 = 53248
static constexpr int EXP_STR = 105;
static constexpr int BSM_BYTES = 128 * EXP_STR * 4; // 53760

__device__ float g_lie[(size_t)131072 * MSZ];      // 52.4 MB scratch

DI void fma2(ull& d, ull a, ull b) { asm("fma.rn.f32x2 %0, %1, %2, %0;" : "+l"(d) : "l"(a), "l"(b)); }
DI ull pack2(float v) { ull r; asm("mov.b64 %0, {%1, %1};" : "=l"(r) : "f"(v)); return r; }
DI ull pk(float x, float y) { ull r; asm("mov.b64 %0, {%1, %2};" : "=l"(r) : "f"(x), "f"(y)); return r; }
DI float2 unpk(ull v) { float2 f; asm("mov.b64 {%0, %1}, %2;" : "=f"(f.x), "=f"(f.y) : "l"(v)); return f; }

DI void cvt_split(float x, float y, uint32_t& hi, uint32_t& lo) {
    __nv_bfloat162 h = __floats2bfloat162_rn(x, y);
    __nv_bfloat162 l = __floats2bfloat162_rn(x - __bfloat162float(h.x), y - __bfloat162float(h.y));
    hi = *reinterpret_cast<uint32_t*>(&h);
    lo = *reinterpret_cast<uint32_t*>(&l);
}

DI void mma16816(float* d, const uint32_t* a, uint32_t b0, uint32_t b1) {
    asm volatile("mma.sync.aligned.m16n8k16.row.col.f32.bf16.bf16.f32 "
        "{%0,%1,%2,%3}, {%4,%5,%6,%7}, {%8,%9}, {%0,%1,%2,%3};"
        : "+f"(d[0]), "+f"(d[1]), "+f"(d[2]), "+f"(d[3])
        : "r"(a[0]), "r"(a[1]), "r"(a[2]), "r"(a[3]), "r"(b0), "r"(b1));
}

// ---------------- Kernel A: lie_alg = z @ basis (split-bf16 mma.sync) ----------------
extern "C" __global__ void __launch_bounds__(256, 2)
lie_gemm(const float* __restrict__ z, const float* __restrict__ basis)
{
    extern __shared__ uint32_t sm[];
    const int tid = threadIdx.x, lane = tid & 31, w = tid >> 5;
    const int g = lane >> 2, q = lane & 3;
    const size_t row0 = (size_t)blockIdx.x * 128 + w * 16 + g;
    const float* zr0 = z + row0 * ZDIM;
    const float* zr1 = zr0 + 8 * ZDIM;

    float acc[NT][4];
#pragma unroll
    for (int nt = 0; nt < NT; nt++) { acc[nt][0]=0.f; acc[nt][1]=0.f; acc[nt][2]=0.f; acc[nt][3]=0.f; }

    for (int c = 0; c < 4; c++) {
        __syncthreads();
        // zero the pad slice nt=12 (covers n=100..103 lanes); 256 threads cover 8x32 slots
        {
            int t = tid >> 5, ln = tid & 31;
            ((uint4*)sm)[(t * NT + 12) * 32 + ln] = make_uint4(0u, 0u, 0u, 0u);
        }
        // stage basis chunk [128k x 100n] in fragment order: slot[t][nt][lane] = (b0h,b1h,b0l,b1l)
        const float* bc = basis + (size_t)c * 128 * MSZ;
        for (int i = tid; i < 6400; i += 256) {          // 64 k-pairs x 100 n
            int n = i % 100, pr = i / 100;
            int t = pr >> 3, pw = pr & 7, half = pw >> 2, qq = pw & 3;
            float v0 = bc[(size_t)(2 * pr) * MSZ + n];
            float v1 = bc[(size_t)(2 * pr + 1) * MSZ + n];
            uint32_t hi, lo;
            cvt_split(v0, v1, hi, lo);
            int base = (((t * NT) + (n >> 3)) * 32 + ((n & 7) * 4 + qq)) * 4;
            sm[base + half] = hi;
            sm[base + 2 + half] = lo;
        }
        __syncthreads();

        for (int t = 0; t < 8; t++) {
            const int kb = c * 128 + t * 16 + 2 * q;
            float2 a00 = *(const float2*)(zr0 + kb);
            float2 a01 = *(const float2*)(zr0 + kb + 8);
            float2 a10 = *(const float2*)(zr1 + kb);
            float2 a11 = *(const float2*)(zr1 + kb + 8);
            uint32_t Ah[4], Al[4];
            cvt_split(a00.x, a00.y, Ah[0], Al[0]);   // (row g,   k lo)
            cvt_split(a10.x, a10.y, Ah[1], Al[1]);   // (row g+8, k lo)
            cvt_split(a01.x, a01.y, Ah[2], Al[2]);   // (row g,   k hi)
            cvt_split(a11.x, a11.y, Ah[3], Al[3]);   // (row g+8, k hi)
            const uint4* bs = (const uint4*)sm + (size_t)(t * NT) * 32 + lane;
#pragma unroll
            for (int nt = 0; nt < NT; nt++) {
                uint4 bb = bs[nt * 32];
                mma16816(acc[nt], Ah, bb.x, bb.y);   // hi*hi
                mma16816(acc[nt], Ah, bb.z, bb.w);   // hi*lo
                mma16816(acc[nt], Al, bb.x, bb.y);   // lo*hi
            }
        }
    }
    // epilogue: fragment -> g_lie (STG.64, guarded at n pad)
#pragma unroll
    for (int nt = 0; nt < NT; nt++) {
        int col = nt * 8 + 2 * q;
        if (col < MSZ) {
            *(float2*)(g_lie + row0 * MSZ + col)       = make_float2(acc[nt][0], acc[nt][1]);
            *(float2*)(g_lie + (row0 + 8) * MSZ + col) = make_float2(acc[nt][2], acc[nt][3]);
        }
    }
}

// ---------------- Kernel B: out = expm(lie_alg), deg-6 Taylor, Paterson-Stockmeyer ----------------
// E = I + A + A^2/2 + A^3/6 + A^3*(A/24 + A^2/120 + A^3/720); 2 threads/matrix, f32x2 math.
extern "C" __global__ void __launch_bounds__(256, 1)
lie_expm(float* __restrict__ out)
{
    extern __shared__ float sA[];
    const int tid = threadIdx.x;
    const size_t blk = (size_t)blockIdx.x * 128;

    for (int i = tid; i < 128 * MSZ; i += 256) {
        int r = i / MSZ, cc = i - r * MSZ;
        sA[r * EXP_STR + cc] = g_lie[blk * MSZ + i];
    }
    __syncthreads();

    const int m  = tid >> 1;
    const int h  = tid & 1;
    const int i0 = 5 * h;
    const int mb = m * EXP_STR;

    ull acc2[5][5], acc3[5][5];
#pragma unroll
    for (int ii = 0; ii < 5; ii++)
#pragma unroll
        for (int jp = 0; jp < 5; jp++) { acc2[ii][jp] = 0ull; acc3[ii][jp] = 0ull; }

    // A^2 (own rows)
#pragma unroll
    for (int kp = 0; kp < 5; kp++) {
        const int k0 = 2 * kp, k1 = k0 + 1;
        ull r0[5], r1[5];
#pragma unroll
        for (int jp = 0; jp < 5; jp++) {
            r0[jp] = pk(sA[mb + k0 * 10 + 2 * jp], sA[mb + k0 * 10 + 2 * jp + 1]);
            r1[jp] = pk(sA[mb + k1 * 10 + 2 * jp], sA[mb + k1 * 10 + 2 * jp + 1]);
        }
#pragma unroll
        for (int ii = 0; ii < 5; ii++) {
            ull z0 = pack2(sA[mb + (i0 + ii) * 10 + k0]);
            ull z1 = pack2(sA[mb + (i0 + ii) * 10 + k1]);
#pragma unroll
            for (int jp = 0; jp < 5; jp++) { fma2(acc2[ii][jp], z0, r0[jp]); fma2(acc2[ii][jp], z1, r1[jp]); }
        }
    }
    // A^3 = A^2 @ A (left operand from registers)
#pragma unroll
    for (int kp = 0; kp < 5; kp++) {
        const int k0 = 2 * kp, k1 = k0 + 1;
        ull r0[5], r1[5];
#pragma unroll
        for (int jp = 0; jp < 5; jp++) {
            r0[jp] = pk(sA[mb + k0 * 10 + 2 * jp], sA[mb + k0 * 10 + 2 * jp + 1]);
            r1[jp] = pk(sA[mb + k1 * 10 + 2 * jp], sA[mb + k1 * 10 + 2 * jp + 1]);
        }
#pragma unroll
        for (int ii = 0; ii < 5; ii++) {
            float2 f = unpk(acc2[ii][kp]);
            ull z0 = pack2(f.x), z1 = pack2(f.y);
#pragma unroll
            for (int jp = 0; jp < 5; jp++) { fma2(acc3[ii][jp], z0, r0[jp]); fma2(acc3[ii][jp], z1, r1[jp]); }
        }
    }
    __syncthreads();   // matmul reads of A done

    // W = A/24 + A^2/120 + A^3/720 -> sA (own rows);  U = I + A + A^2/2 + A^3/6 -> acc2
    {
        const float c2 = 0.5f, c3 = 1.f/6.f, c4 = 1.f/24.f, c5 = 1.f/120.f, c6 = 1.f/720.f;
#pragma unroll
        for (int ii = 0; ii < 5; ii++) {
            const int gi = i0 + ii;
#pragma unroll
            for (int jp = 0; jp < 5; jp++) {
                float ax = sA[mb + gi * 10 + 2 * jp];
                float ay = sA[mb + gi * 10 + 2 * jp + 1];
                float2 b2 = unpk(acc2[ii][jp]);
                float2 b3 = unpk(acc3[ii][jp]);
                float wx = ax * c4 + b2.x * c5 + b3.x * c6;
                float wy = ay * c4 + b2.y * c5 + b3.y * c6;
                float ux = (gi == 2 * jp     ? 1.f : 0.f) + ax + b2.x * c2 + b3.x * c3;
                float uy = (gi == 2 * jp + 1 ? 1.f : 0.f) + ay + b2.y * c2 + b3.y * c3;
                sA[mb + gi * 10 + 2 * jp]     = wx;
                sA[mb + gi * 10 + 2 * jp + 1] = wy;
                acc2[ii][jp] = pk(ux, uy);
            }
        }
    }
    __syncthreads();   // W complete

    // E = U + A^3 @ W
#pragma unroll
    for (int kp = 0; kp < 5; kp++) {
        const int k0 = 2 * kp, k1 = k0 + 1;
        ull r0[5], r1[5];
#pragma unroll
        for (int jp = 0; jp < 5; jp++) {
            r0[jp] = pk(sA[mb + k0 * 10 + 2 * jp], sA[mb + k0 * 10 + 2 * jp + 1]);
            r1[jp] = pk(sA[mb + k1 * 10 + 2 * jp], sA[mb + k1 * 10 + 2 * jp + 1]);
        }
#pragma unroll
        for (int ii = 0; ii < 5; ii++) {
            float2 f = unpk(acc3[ii][kp]);
            ull z0 = pack2(f.x), z1 = pack2(f.y);
#pragma unroll
            for (int jp = 0; jp < 5; jp++) { fma2(acc2[ii][jp], z0, r0[jp]); fma2(acc2[ii][jp], z1, r1[jp]); }
        }
    }

    // store own 5 rows (50 contiguous floats)
    float* op = out + (blk + m) * MSZ + i0 * 10;
#pragma unroll
    for (int ii = 0; ii < 5; ii++)
#pragma unroll
        for (int jp = 0; jp < 5; jp++) {
            float2 v = unpk(acc2[ii][jp]);
            op[ii * 10 + 2 * jp]     = v.x;
            op[ii * 10 + 2 * jp + 1] = v.y;
        }
}

// ---------------- launch ----------------
extern "C" void kernel_launch(void* const* d_in, const int* in_sizes, int n_in,
                              void* d_out, int out_size)
{
    const float* z     = (const float*)d_in[0];   // [B, 512]
    const float* basis = (const float*)d_in[1];   // [512, 10, 10]
    float* out = (float*)d_out;                   // [B, 10, 10]

    int B = in_sizes[0] / ZDIM;                   // 131072
    int grid = B / 128;                           // 1024

    cudaFuncSetAttribute(lie_gemm, cudaFuncAttributeMaxDynamicSharedMemorySize, ASM_BYTES);
    cudaFuncSetAttribute(lie_expm, cudaFuncAttributeMaxDynamicSharedMemorySize, BSM_BYTES);

    lie_gemm<<<grid, 256, ASM_BYTES>>>(z, basis);
    lie_expm<<<grid, 256, BSM_BYTES>>>(out);
}

// round 6
// speedup vs baseline: 1.9701x; 1.2895x over previous
#include <cuda_runtime.h>
#include <cuda_fp16.h>
#include <cstdint>
#include <cstddef>

#define DI __device__ __forceinline__
typedef unsigned long long ull;

static constexpr int ZDIM = 512;
static constexpr int MSZ  = 100;
static constexpr int NT   = 13;                    // n8 tiles (104 >= 100)
static constexpr int ASM_BYTES = 8 * NT * 32 * 16; // B-stage: [8 k16][13 nt][32 lanes] uint4 = 53248
static constexpr int EXP_STR = 106;                // even: LDS.64-aligned; 106*m mod 32 conflict-free
static constexpr int MATS_B  = 64;                 // matrices per expm CTA (128 threads)
static constexpr int BSM_BYTES = MATS_B * EXP_STR * 4;  // 27136

__device__ float g_lie[(size_t)131072 * MSZ];      // 52.4 MB scratch

DI void fma2(ull& d, ull a, ull b) { asm("fma.rn.f32x2 %0, %1, %2, %0;" : "+l"(d) : "l"(a), "l"(b)); }
DI ull pack2(float v) { ull r; asm("mov.b64 %0, {%1, %1};" : "=l"(r) : "f"(v)); return r; }
DI ull pk(float x, float y) { ull r; asm("mov.b64 %0, {%1, %2};" : "=l"(r) : "f"(x), "f"(y)); return r; }
DI float2 unpk(ull v) { float2 f; asm("mov.b64 {%0, %1}, %2;" : "=f"(f.x), "=f"(f.y) : "l"(v)); return f; }
DI ull lds2(const float* p) { float2 v = *(const float2*)p; return pk(v.x, v.y); }  // one LDS.64

// split fp32 pair into f16x2 hi + f16x2 residual-lo
DI void cvt_split(float x, float y, uint32_t& hi, uint32_t& lo) {
    __half2 h = __floats2half2_rn(x, y);
    __half2 l = __floats2half2_rn(x - __low2float(h), y - __high2float(h));
    hi = *reinterpret_cast<uint32_t*>(&h);
    lo = *reinterpret_cast<uint32_t*>(&l);
}

DI void mma16816(float* d, const uint32_t* a, uint32_t b0, uint32_t b1) {
    asm volatile("mma.sync.aligned.m16n8k16.row.col.f32.f16.f16.f32 "
        "{%0,%1,%2,%3}, {%4,%5,%6,%7}, {%8,%9}, {%0,%1,%2,%3};"
        : "+f"(d[0]), "+f"(d[1]), "+f"(d[2]), "+f"(d[3])
        : "r"(a[0]), "r"(a[1]), "r"(a[2]), "r"(a[3]), "r"(b0), "r"(b1));
}

// ---------------- Kernel A: lie_alg = z @ basis (split-fp16 3-pass mma.sync) ----------------
extern "C" __global__ void __launch_bounds__(256, 2)
lie_gemm(const float* __restrict__ z, const float* __restrict__ basis)
{
    extern __shared__ uint32_t sm[];
    const int tid = threadIdx.x, lane = tid & 31, w = tid >> 5;
    const int g = lane >> 2, q = lane & 3;
    const size_t row0 = (size_t)blockIdx.x * 128 + w * 16 + g;
    const float* zr0 = z + row0 * ZDIM;
    const float* zr1 = zr0 + 8 * ZDIM;

    float acc[NT][4];
#pragma unroll
    for (int nt = 0; nt < NT; nt++) { acc[nt][0]=0.f; acc[nt][1]=0.f; acc[nt][2]=0.f; acc[nt][3]=0.f; }

    // zero pad slice nt=12 ONCE (lanes 16..31 = n 100..103 stay zero; lanes 0..15 restaged per chunk)
    {
        int t = tid >> 5, ln = tid & 31;
        ((uint4*)sm)[(t * NT + 12) * 32 + ln] = make_uint4(0u, 0u, 0u, 0u);
    }

    // prefetch first k16-tile of z fragments
    float2 p00, p01, p10, p11;
    {
        const int kb = 2 * q;
        p00 = *(const float2*)(zr0 + kb);  p01 = *(const float2*)(zr0 + kb + 8);
        p10 = *(const float2*)(zr1 + kb);  p11 = *(const float2*)(zr1 + kb + 8);
    }

    for (int c = 0; c < 4; c++) {
        __syncthreads();   // previous chunk's B reads complete before restage (also covers pad zeroing)
        // stage basis chunk [128k x 100n] in fragment order: slot[t][nt][lane] = (b0h,b1h,b0l,b1l)
        const float* bc = basis + (size_t)c * 128 * MSZ;
        for (int i = tid; i < 6400; i += 256) {          // 64 k-pairs x 100 n
            int n = i % 100, pr = i / 100;
            int t = pr >> 3, pw = pr & 7, half = pw >> 2, qq = pw & 3;
            float v0 = bc[(size_t)(2 * pr) * MSZ + n];
            float v1 = bc[(size_t)(2 * pr + 1) * MSZ + n];
            uint32_t hi, lo;
            cvt_split(v0, v1, hi, lo);
            int base = (((t * NT) + (n >> 3)) * 32 + ((n & 7) * 4 + qq)) * 4;
            sm[base + half] = hi;
            sm[base + 2 + half] = lo;
        }
        __syncthreads();

        for (int t = 0; t < 8; t++) {
            // consume prefetched fragments
            uint32_t Ah[4], Al[4];
            cvt_split(p00.x, p00.y, Ah[0], Al[0]);   // (row g,   k lo)
            cvt_split(p10.x, p10.y, Ah[1], Al[1]);   // (row g+8, k lo)
            cvt_split(p01.x, p01.y, Ah[2], Al[2]);   // (row g,   k hi)
            cvt_split(p11.x, p11.y, Ah[3], Al[3]);   // (row g+8, k hi)
            // prefetch next k16-tile (z only -> safe across chunk restage)
            const int ktn = c * 128 + t * 16 + 16;
            if (ktn < ZDIM) {
                const int kb = ktn + 2 * q;
                p00 = *(const float2*)(zr0 + kb);  p01 = *(const float2*)(zr0 + kb + 8);
                p10 = *(const float2*)(zr1 + kb);  p11 = *(const float2*)(zr1 + kb + 8);
            }
            const uint4* bs = (const uint4*)sm + (size_t)(t * NT) * 32 + lane;
#pragma unroll
            for (int nt = 0; nt < NT; nt++) {
                uint4 bb = bs[nt * 32];
                mma16816(acc[nt], Ah, bb.x, bb.y);   // hi*hi
                mma16816(acc[nt], Ah, bb.z, bb.w);   // hi*lo
                mma16816(acc[nt], Al, bb.x, bb.y);   // lo*hi
            }
        }
    }
    // epilogue: fragment -> g_lie (STG.64, guarded at n pad)
#pragma unroll
    for (int nt = 0; nt < NT; nt++) {
        int col = nt * 8 + 2 * q;
        if (col < MSZ) {
            *(float2*)(g_lie + row0 * MSZ + col)       = make_float2(acc[nt][0], acc[nt][1]);
            *(float2*)(g_lie + (row0 + 8) * MSZ + col) = make_float2(acc[nt][2], acc[nt][3]);
        }
    }
}

// ---------------- Kernel B: out = expm(lie_alg), deg-6 Taylor, Paterson-Stockmeyer ----------------
// E = I + A + A^2/2 + A^3/6 + A^3*(A/24 + A^2/120 + A^3/720); 2 threads/matrix, f32x2 math.
extern "C" __global__ void __launch_bounds__(128, 3)
lie_expm(float* __restrict__ out)
{
    extern __shared__ float sA[];
    const int tid = threadIdx.x;
    const size_t blk = (size_t)blockIdx.x * MATS_B;

    // load A tile (64 x 100 floats) via float2, coalesced; both src and dst 8B-aligned
    {
        const float2* src = (const float2*)(g_lie + blk * MSZ);
        for (int i = tid; i < MATS_B * MSZ / 2; i += 128) {
            int r = i / 50, cc = (i - r * 50) * 2;
            *(float2*)(sA + r * EXP_STR + cc) = src[i];
        }
    }
    __syncthreads();

    const int m  = tid >> 1;
    const int h  = tid & 1;
    const int i0 = 5 * h;
    const int mb = m * EXP_STR;

    ull acc2[5][5], acc3[5][5];
#pragma unroll
    for (int ii = 0; ii < 5; ii++)
#pragma unroll
        for (int jp = 0; jp < 5; jp++) { acc2[ii][jp] = 0ull; acc3[ii][jp] = 0ull; }

    // A^2 (own rows): one LDS.64 per operand pair
#pragma unroll
    for (int kp = 0; kp < 5; kp++) {
        const int k0 = 2 * kp, k1 = k0 + 1;
        ull r0[5], r1[5];
#pragma unroll
        for (int jp = 0; jp < 5; jp++) {
            r0[jp] = lds2(sA + mb + k0 * 10 + 2 * jp);
            r1[jp] = lds2(sA + mb + k1 * 10 + 2 * jp);
        }
#pragma unroll
        for (int ii = 0; ii < 5; ii++) {
            float2 za = *(const float2*)(sA + mb + (i0 + ii) * 10 + k0);
            ull z0 = pack2(za.x), z1 = pack2(za.y);
#pragma unroll
            for (int jp = 0; jp < 5; jp++) { fma2(acc2[ii][jp], z0, r0[jp]); fma2(acc2[ii][jp], z1, r1[jp]); }
        }
    }
    // A^3 = A^2 @ A (left operand from registers)
#pragma unroll
    for (int kp = 0; kp < 5; kp++) {
        const int k0 = 2 * kp, k1 = k0 + 1;
        ull r0[5], r1[5];
#pragma unroll
        for (int jp = 0; jp < 5; jp++) {
            r0[jp] = lds2(sA + mb + k0 * 10 + 2 * jp);
            r1[jp] = lds2(sA + mb + k1 * 10 + 2 * jp);
        }
#pragma unroll
        for (int ii = 0; ii < 5; ii++) {
            float2 f = unpk(acc2[ii][kp]);
            ull z0 = pack2(f.x), z1 = pack2(f.y);
#pragma unroll
            for (int jp = 0; jp < 5; jp++) { fma2(acc3[ii][jp], z0, r0[jp]); fma2(acc3[ii][jp], z1, r1[jp]); }
        }
    }
    __syncthreads();   // matmul reads of A done

    // W = A/24 + A^2/120 + A^3/720 -> sA (own rows);  U = I + A + A^2/2 + A^3/6 -> acc2
    {
        const float c2 = 0.5f, c3 = 1.f/6.f, c4 = 1.f/24.f, c5 = 1.f/120.f, c6 = 1.f/720.f;
#pragma unroll
        for (int ii = 0; ii < 5; ii++) {
            const int gi = i0 + ii;
#pragma unroll
            for (int jp = 0; jp < 5; jp++) {
                float2 a = *(const float2*)(sA + mb + gi * 10 + 2 * jp);
                float2 b2 = unpk(acc2[ii][jp]);
                float2 b3 = unpk(acc3[ii][jp]);
                float wx = a.x * c4 + b2.x * c5 + b3.x * c6;
                float wy = a.y * c4 + b2.y * c5 + b3.y * c6;
                float ux = (gi == 2 * jp     ? 1.f : 0.f) + a.x + b2.x * c2 + b3.x * c3;
                float uy = (gi == 2 * jp + 1 ? 1.f : 0.f) + a.y + b2.y * c2 + b3.y * c3;
                *(float2*)(sA + mb + gi * 10 + 2 * jp) = make_float2(wx, wy);
                acc2[ii][jp] = pk(ux, uy);
            }
        }
    }
    __syncthreads();   // W complete

    // E = U + A^3 @ W
#pragma unroll
    for (int kp = 0; kp < 5; kp++) {
        const int k0 = 2 * kp, k1 = k0 + 1;
        ull r0[5], r1[5];
#pragma unroll
        for (int jp = 0; jp < 5; jp++) {
            r0[jp] = lds2(sA + mb + k0 * 10 + 2 * jp);
            r1[jp] = lds2(sA + mb + k1 * 10 + 2 * jp);
        }
#pragma unroll
        for (int ii = 0; ii < 5; ii++) {
            float2 f = unpk(acc3[ii][kp]);
            ull z0 = pack2(f.x), z1 = pack2(f.y);
#pragma unroll
            for (int jp = 0; jp < 5; jp++) { fma2(acc2[ii][jp], z0, r0[jp]); fma2(acc2[ii][jp], z1, r1[jp]); }
        }
    }

    // store own 5 rows (50 contiguous floats, 8B-aligned)
    float* op = out + (blk + m) * MSZ + i0 * 10;
#pragma unroll
    for (int ii = 0; ii < 5; ii++)
#pragma unroll
        for (int jp = 0; jp < 5; jp++) {
            float2 v = unpk(acc2[ii][jp]);
            *(float2*)(op + ii * 10 + 2 * jp) = v;
        }
}

// ---------------- launch ----------------
extern "C" void kernel_launch(void* const* d_in, const int* in_sizes, int n_in,
                              void* d_out, int out_size)
{
    const float* z     = (const float*)d_in[0];   // [B, 512]
    const float* basis = (const float*)d_in[1];   // [512, 10, 10]
    float* out = (float*)d_out;                   // [B, 10, 10]

    int B = in_sizes[0] / ZDIM;                   // 131072

    cudaFuncSetAttribute(lie_gemm, cudaFuncAttributeMaxDynamicSharedMemorySize, ASM_BYTES);
    cudaFuncSetAttribute(lie_expm, cudaFuncAttributeMaxDynamicSharedMemorySize, BSM_BYTES);

    lie_gemm<<<B / 128, 256, ASM_BYTES>>>(z, basis);
    lie_expm<<<B / MATS_B, 128, BSM_BYTES>>>(out);
}

// round 7
// speedup vs baseline: 2.0194x; 1.0250x over previous
#include <cuda_runtime.h>
#include <cuda_fp16.h>
#include <cstdint>
#include <cstddef>

#define DI __device__ __forceinline__
typedef unsigned long long ull;

static constexpr int ZDIM = 512;
static constexpr int MSZ  = 100;
static constexpr int NT   = 13;                      // n8 tiles (104 >= 100)
static constexpr int EXP_STR   = 106;                // even (LDS.64 aligned), conflict-free residues
static constexpr int SA_FLOATS = 128 * EXP_STR;      // 13568 floats = 54272 B
static constexpr int SMEM_DYN  = 2 * SA_FLOATS * 4;  // 108544 B (sA + sC/B-stage union)

DI void fma2(ull& d, ull a, ull b) { asm("fma.rn.f32x2 %0, %1, %2, %0;" : "+l"(d) : "l"(a), "l"(b)); }
DI ull pack2(float v) { ull r; asm("mov.b64 %0, {%1, %1};" : "=l"(r) : "f"(v)); return r; }
DI ull pk(float x, float y) { ull r; asm("mov.b64 %0, {%1, %2};" : "=l"(r) : "f"(x), "f"(y)); return r; }
DI float2 unpk(ull v) { float2 f; asm("mov.b64 {%0, %1}, %2;" : "=f"(f.x), "=f"(f.y) : "l"(v)); return f; }
DI ull lds2(const float* p) { float2 v = *(const float2*)p; return pk(v.x, v.y); }

// split fp32 pair into f16x2 hi + f16x2 residual-lo
DI void cvt_split(float x, float y, uint32_t& hi, uint32_t& lo) {
    __half2 h = __floats2half2_rn(x, y);
    __half2 l = __floats2half2_rn(x - __low2float(h), y - __high2float(h));
    hi = *reinterpret_cast<uint32_t*>(&h);
    lo = *reinterpret_cast<uint32_t*>(&l);
}

DI void mma16816(float* d, const uint32_t* a, uint32_t b0, uint32_t b1) {
    asm volatile("mma.sync.aligned.m16n8k16.row.col.f32.f16.f16.f32 "
        "{%0,%1,%2,%3}, {%4,%5,%6,%7}, {%8,%9}, {%0,%1,%2,%3};"
        : "+f"(d[0]), "+f"(d[1]), "+f"(d[2]), "+f"(d[3])
        : "r"(a[0]), "r"(a[1]), "r"(a[2]), "r"(a[3]), "r"(b0), "r"(b1));
}

extern "C" __global__ void __launch_bounds__(256, 2)
lie_fused(const float* __restrict__ z, const float* __restrict__ basis, float* __restrict__ out)
{
    extern __shared__ float smem[];
    float*    sA  = smem;                 // expm working set (gemm epilogue target)
    float*    sC  = smem + SA_FLOATS;     // A^3 buffer; union with B-stage during gemm
    uint32_t* smB = (uint32_t*)sC;        // B-stage: [8 k16][13 nt][32 lanes] uint4 (53248 B)

    const int tid = threadIdx.x, lane = tid & 31, w = tid >> 5;
    const int g = lane >> 2, q = lane & 3;
    const size_t rowBase = (size_t)blockIdx.x * 128;
    const size_t row0 = rowBase + w * 16 + g;
    const float* zr0 = z + row0 * ZDIM;
    const float* zr1 = zr0 + 8 * ZDIM;

    // ================= GEMM phase: lie_alg = z_tile @ basis (split-fp16, 3-pass) =================
    float acc[NT][4];
#pragma unroll
    for (int nt = 0; nt < NT; nt++) { acc[nt][0]=0.f; acc[nt][1]=0.f; acc[nt][2]=0.f; acc[nt][3]=0.f; }

    // zero pad lanes 16..31 of the nt=12 slices, once (n=100..103 stay zero; never re-written)
    if (tid < 128) {
        int t = tid >> 4, ln = 16 + (tid & 15);
        ((uint4*)smB)[(t * NT + 12) * 32 + ln] = make_uint4(0u, 0u, 0u, 0u);
    }

    // prefetch first k16-tile of z fragments
    float2 p00, p01, p10, p11;
    {
        const int kb = 2 * q;
        p00 = *(const float2*)(zr0 + kb);  p01 = *(const float2*)(zr0 + kb + 8);
        p10 = *(const float2*)(zr1 + kb);  p11 = *(const float2*)(zr1 + kb + 8);
    }

    for (int c = 0; c < 4; c++) {
        __syncthreads();   // previous chunk's B reads done (also orders pad-zero before first stage)
        // stage basis chunk [128k x 100n] in fragment order: slot[t][nt][lane] = (b0h,b1h,b0l,b1l)
        const float* bc = basis + (size_t)c * 128 * MSZ;
        for (int i = tid; i < 6400; i += 256) {          // 64 k-pairs x 100 n
            int n = i % 100, pr = i / 100;
            int t = pr >> 3, pw = pr & 7, half = pw >> 2, qq = pw & 3;
            float v0 = bc[(size_t)(2 * pr) * MSZ + n];
            float v1 = bc[(size_t)(2 * pr + 1) * MSZ + n];
            uint32_t hi, lo;
            cvt_split(v0, v1, hi, lo);
            int base = (((t * NT) + (n >> 3)) * 32 + ((n & 7) * 4 + qq)) * 4;
            smB[base + half]     = hi;
            smB[base + 2 + half] = lo;
        }
        __syncthreads();

        for (int t = 0; t < 8; t++) {
            uint32_t Ah[4], Al[4];
            cvt_split(p00.x, p00.y, Ah[0], Al[0]);   // (row g,   k lo)
            cvt_split(p10.x, p10.y, Ah[1], Al[1]);   // (row g+8, k lo)
            cvt_split(p01.x, p01.y, Ah[2], Al[2]);   // (row g,   k hi)
            cvt_split(p11.x, p11.y, Ah[3], Al[3]);   // (row g+8, k hi)
            const int ktn = c * 128 + t * 16 + 16;
            if (ktn < ZDIM) {
                const int kb = ktn + 2 * q;
                p00 = *(const float2*)(zr0 + kb);  p01 = *(const float2*)(zr0 + kb + 8);
                p10 = *(const float2*)(zr1 + kb);  p11 = *(const float2*)(zr1 + kb + 8);
            }
            const uint4* bs = (const uint4*)smB + (size_t)(t * NT) * 32 + lane;

            // group 1: nt 0..6 — pass-major (dependency distance 7 on each acc[nt])
            {
                uint4 bb[7];
#pragma unroll
                for (int j = 0; j < 7; j++) bb[j] = bs[j * 32];
#pragma unroll
                for (int j = 0; j < 7; j++) mma16816(acc[j], Ah, bb[j].x, bb[j].y);   // hi*hi
#pragma unroll
                for (int j = 0; j < 7; j++) mma16816(acc[j], Al, bb[j].x, bb[j].y);   // lo*hi
#pragma unroll
                for (int j = 0; j < 7; j++) mma16816(acc[j], Ah, bb[j].z, bb[j].w);   // hi*lo
            }
            // group 2: nt 7..12
            {
                uint4 bb[6];
#pragma unroll
                for (int j = 0; j < 6; j++) bb[j] = bs[(7 + j) * 32];
#pragma unroll
                for (int j = 0; j < 6; j++) mma16816(acc[7 + j], Ah, bb[j].x, bb[j].y);
#pragma unroll
                for (int j = 0; j < 6; j++) mma16816(acc[7 + j], Al, bb[j].x, bb[j].y);
#pragma unroll
                for (int j = 0; j < 6; j++) mma16816(acc[7 + j], Ah, bb[j].z, bb[j].w);
            }
        }
    }

    // epilogue: fragments -> sA in expm layout (row-local stride EXP_STR)
    {
        const int rl0 = w * 16 + g;
#pragma unroll
        for (int nt = 0; nt < NT; nt++) {
            int col = nt * 8 + 2 * q;
            if (col < MSZ) {
                *(float2*)(sA + rl0 * EXP_STR + col)       = make_float2(acc[nt][0], acc[nt][1]);
                *(float2*)(sA + (rl0 + 8) * EXP_STR + col) = make_float2(acc[nt][2], acc[nt][3]);
            }
        }
    }
    __syncthreads();   // lie_alg complete in sA; B-stage dead -> sC reusable

    // ================= expm phase: E = I + A + A^2/2 + A^3/6 + A^3*(A/24 + A^2/120 + A^3/720) =====
    {
        const int m  = tid >> 1;       // local matrix 0..127
        const int h  = tid & 1;
        const int i0 = 5 * h;
        const int mb = m * EXP_STR;

        ull acc2[5][5];
#pragma unroll
        for (int ii = 0; ii < 5; ii++)
#pragma unroll
            for (int jp = 0; jp < 5; jp++) acc2[ii][jp] = 0ull;

        // A^2 (own rows) -> acc2
#pragma unroll
        for (int kp = 0; kp < 5; kp++) {
            const int k0 = 2 * kp, k1 = k0 + 1;
            ull r0[5], r1[5];
#pragma unroll
            for (int jp = 0; jp < 5; jp++) {
                r0[jp] = lds2(sA + mb + k0 * 10 + 2 * jp);
                r1[jp] = lds2(sA + mb + k1 * 10 + 2 * jp);
            }
#pragma unroll
            for (int ii = 0; ii < 5; ii++) {
                float2 za = *(const float2*)(sA + mb + (i0 + ii) * 10 + k0);
                ull z0 = pack2(za.x), z1 = pack2(za.y);
#pragma unroll
                for (int jp = 0; jp < 5; jp++) { fma2(acc2[ii][jp], z0, r0[jp]); fma2(acc2[ii][jp], z1, r1[jp]); }
            }
        }

        // A^3 = A^2 @ A -> sC (two row-groups to bound register pressure)
#pragma unroll
        for (int grp = 0; grp < 2; grp++) {
            const int gbase = grp * 3;
            const int rows  = grp == 0 ? 3 : 2;
            ull a3[3][5];
#pragma unroll
            for (int ii = 0; ii < 3; ii++)
#pragma unroll
                for (int jp = 0; jp < 5; jp++) a3[ii][jp] = 0ull;
#pragma unroll
            for (int kp = 0; kp < 5; kp++) {
                const int k0 = 2 * kp, k1 = k0 + 1;
                ull r0[5], r1[5];
#pragma unroll
                for (int jp = 0; jp < 5; jp++) {
                    r0[jp] = lds2(sA + mb + k0 * 10 + 2 * jp);
                    r1[jp] = lds2(sA + mb + k1 * 10 + 2 * jp);
                }
#pragma unroll
                for (int ii = 0; ii < 3; ii++) {
                    if (ii < rows) {
                        float2 f = unpk(acc2[gbase + ii][kp]);
                        ull z0 = pack2(f.x), z1 = pack2(f.y);
#pragma unroll
                        for (int jp = 0; jp < 5; jp++) { fma2(a3[ii][jp], z0, r0[jp]); fma2(a3[ii][jp], z1, r1[jp]); }
                    }
                }
            }
#pragma unroll
            for (int ii = 0; ii < 3; ii++) {
                if (ii < rows) {
                    const int gi = i0 + gbase + ii;
#pragma unroll
                    for (int jp = 0; jp < 5; jp++)
                        *(float2*)(sC + mb + gi * 10 + 2 * jp) = unpk(a3[ii][jp]);
                }
            }
        }
        __syncthreads();   // all matmul reads of A (sA) complete before W overwrite

        // W = A/24 + A^2/120 + A^3/720 -> sA (own rows); U = I + A + A^2/2 + A^3/6 -> acc2
        {
            const float c2 = 0.5f, c3 = 1.f/6.f, c4 = 1.f/24.f, c5 = 1.f/120.f, c6 = 1.f/720.f;
#pragma unroll
            for (int ii = 0; ii < 5; ii++) {
                const int gi = i0 + ii;
#pragma unroll
                for (int jp = 0; jp < 5; jp++) {
                    float2 a  = *(const float2*)(sA + mb + gi * 10 + 2 * jp);
                    float2 b3 = *(const float2*)(sC + mb + gi * 10 + 2 * jp);
                    float2 b2 = unpk(acc2[ii][jp]);
                    float wx = a.x * c4 + b2.x * c5 + b3.x * c6;
                    float wy = a.y * c4 + b2.y * c5 + b3.y * c6;
                    float ux = (gi == 2 * jp     ? 1.f : 0.f) + a.x + b2.x * c2 + b3.x * c3;
                    float uy = (gi == 2 * jp + 1 ? 1.f : 0.f) + a.y + b2.y * c2 + b3.y * c3;
                    *(float2*)(sA + mb + gi * 10 + 2 * jp) = make_float2(wx, wy);
                    acc2[ii][jp] = pk(ux, uy);
                }
            }
        }
        __syncthreads();   // W complete in sA

        // E = U + A^3 @ W  (A^3 left operand from sC own rows; W rows from sA)
#pragma unroll
        for (int kp = 0; kp < 5; kp++) {
            const int k0 = 2 * kp, k1 = k0 + 1;
            ull r0[5], r1[5];
#pragma unroll
            for (int jp = 0; jp < 5; jp++) {
                r0[jp] = lds2(sA + mb + k0 * 10 + 2 * jp);
                r1[jp] = lds2(sA + mb + k1 * 10 + 2 * jp);
            }
#pragma unroll
            for (int ii = 0; ii < 5; ii++) {
                float2 f = *(const float2*)(sC + mb + (i0 + ii) * 10 + k0);
                ull z0 = pack2(f.x), z1 = pack2(f.y);
#pragma unroll
                for (int jp = 0; jp < 5; jp++) { fma2(acc2[ii][jp], z0, r0[jp]); fma2(acc2[ii][jp], z1, r1[jp]); }
            }
        }

        // store own 5 rows (50 contiguous floats)
        float* op = out + (rowBase + m) * MSZ + i0 * 10;
#pragma unroll
        for (int ii = 0; ii < 5; ii++)
#pragma unroll
            for (int jp = 0; jp < 5; jp++)
                *(float2*)(op + ii * 10 + 2 * jp) = unpk(acc2[ii][jp]);
    }
}

// ---------------- launch ----------------
extern "C" void kernel_launch(void* const* d_in, const int* in_sizes, int n_in,
                              void* d_out, int out_size)
{
    const float* z     = (const float*)d_in[0];   // [B, 512]
    const float* basis = (const float*)d_in[1];   // [512, 10, 10]
    float* out = (float*)d_out;                   // [B, 10, 10]

    int B = in_sizes[0] / ZDIM;                   // 131072

    cudaFuncSetAttribute(lie_fused, cudaFuncAttributeMaxDynamicSharedMemorySize, SMEM_DYN);
    lie_fused<<<B / 128, 256, SMEM_DYN>>>(z, basis, out);
}

// round 8
// speedup vs baseline: 2.5308x; 1.2532x over previous
#include <cuda_runtime.h>
#include <cuda_fp16.h>
#include <cstdint>
#include <cstddef>

#define DI __device__ __forceinline__
typedef unsigned long long ull;

static constexpr int ZDIM = 512;
static constexpr int MSZ  = 100;
static constexpr int NT   = 13;                      // n8 tiles (104 >= 100)
static constexpr int TSTEPS = ZDIM / 16;             // 32 k16-tiles
static constexpr int EXP_STR   = 106;                // even (LDS.64 aligned), conflict-free residues
static constexpr int SA_FLOATS = 128 * EXP_STR;      // 13568 floats = 54272 B
static constexpr int SMEM_DYN  = 2 * SA_FLOATS * 4;  // 108544 B (sA + sC)

// basis fragments, fragment-ordered: [t 0..31][nt 0..12][lane 0..31] = (b0h,b1h,b0l,b1l)
__device__ uint4 g_bfrag[TSTEPS * NT * 32];          // 212,992 B (L2-resident)

DI void fma2(ull& d, ull a, ull b) { asm("fma.rn.f32x2 %0, %1, %2, %0;" : "+l"(d) : "l"(a), "l"(b)); }
DI ull pack2(float v) { ull r; asm("mov.b64 %0, {%1, %1};" : "=l"(r) : "f"(v)); return r; }
DI ull pk(float x, float y) { ull r; asm("mov.b64 %0, {%1, %2};" : "=l"(r) : "f"(x), "f"(y)); return r; }
DI float2 unpk(ull v) { float2 f; asm("mov.b64 {%0, %1}, %2;" : "=f"(f.x), "=f"(f.y) : "l"(v)); return f; }
DI ull lds2(const float* p) { float2 v = *(const float2*)p; return pk(v.x, v.y); }

// split fp32 pair into f16x2 hi + f16x2 residual-lo
DI void cvt_split(float x, float y, uint32_t& hi, uint32_t& lo) {
    __half2 h = __floats2half2_rn(x, y);
    __half2 l = __floats2half2_rn(x - __low2float(h), y - __high2float(h));
    hi = *reinterpret_cast<uint32_t*>(&h);
    lo = *reinterpret_cast<uint32_t*>(&l);
}

DI void mma16816(float* d, const uint32_t* a, uint32_t b0, uint32_t b1) {
    asm volatile("mma.sync.aligned.m16n8k16.row.col.f32.f16.f16.f32 "
        "{%0,%1,%2,%3}, {%4,%5,%6,%7}, {%8,%9}, {%0,%1,%2,%3};"
        : "+f"(d[0]), "+f"(d[1]), "+f"(d[2]), "+f"(d[3])
        : "r"(a[0]), "r"(a[1]), "r"(a[2]), "r"(a[3]), "r"(b0), "r"(b1));
}

// ---------- pre-kernel: convert basis -> fragment-ordered split-fp16 global array ----------
extern "C" __global__ void __launch_bounds__(256)
conv_basis(const float* __restrict__ basis)
{
    int s = blockIdx.x * 256 + threadIdx.x;          // 0 .. 13311
    if (s >= TSTEPS * NT * 32) return;
    int t  = s / (NT * 32);
    int r  = s - t * (NT * 32);
    int nt = r >> 5;
    int ln = r & 31;
    int qq = ln & 3;
    int n  = nt * 8 + (ln >> 2);
    uint4 val = make_uint4(0u, 0u, 0u, 0u);
    if (n < MSZ) {
        int k0 = t * 16 + 2 * qq;
        float v0 = basis[(size_t)k0 * MSZ + n];
        float v1 = basis[(size_t)(k0 + 1) * MSZ + n];
        float v2 = basis[(size_t)(k0 + 8) * MSZ + n];
        float v3 = basis[(size_t)(k0 + 9) * MSZ + n];
        cvt_split(v0, v1, val.x, val.z);
        cvt_split(v2, v3, val.y, val.w);
    }
    g_bfrag[s] = val;
}

// ---------- fused kernel: GEMM (split-fp16 3-pass mma.sync) + expm ----------
extern "C" __global__ void __launch_bounds__(256, 2)
lie_fused(const float* __restrict__ z, float* __restrict__ out)
{
    extern __shared__ float smem[];
    float* sA = smem;                 // lie_alg / W working set
    float* sC = smem + SA_FLOATS;     // A^3 buffer

    const int tid = threadIdx.x, lane = tid & 31, w = tid >> 5;
    const int g = lane >> 2, q = lane & 3;
    const size_t rowBase = (size_t)blockIdx.x * 128;
    const size_t row0 = rowBase + w * 16 + g;
    const float* zr0 = z + row0 * ZDIM;
    const float* zr1 = zr0 + 8 * ZDIM;

    // ================= GEMM phase =================
    float acc[NT][4];
#pragma unroll
    for (int nt = 0; nt < NT; nt++) { acc[nt][0]=0.f; acc[nt][1]=0.f; acc[nt][2]=0.f; acc[nt][3]=0.f; }

    // prefetch first k16-tile of z fragments
    float2 p00, p01, p10, p11;
    {
        const int kb = 2 * q;
        p00 = *(const float2*)(zr0 + kb);  p01 = *(const float2*)(zr0 + kb + 8);
        p10 = *(const float2*)(zr1 + kb);  p11 = *(const float2*)(zr1 + kb + 8);
    }

    for (int t = 0; t < TSTEPS; t++) {
        uint32_t Ah[4], Al[4];
        cvt_split(p00.x, p00.y, Ah[0], Al[0]);   // (row g,   k lo)
        cvt_split(p10.x, p10.y, Ah[1], Al[1]);   // (row g+8, k lo)
        cvt_split(p01.x, p01.y, Ah[2], Al[2]);   // (row g,   k hi)
        cvt_split(p11.x, p11.y, Ah[3], Al[3]);   // (row g+8, k hi)
        if (t + 1 < TSTEPS) {
            const int kb = (t + 1) * 16 + 2 * q;
            p00 = *(const float2*)(zr0 + kb);  p01 = *(const float2*)(zr0 + kb + 8);
            p10 = *(const float2*)(zr1 + kb);  p11 = *(const float2*)(zr1 + kb + 8);
        }
        const uint4* __restrict__ bs = g_bfrag + (size_t)t * (NT * 32) + lane;

        // group 1: nt 0..6 — coalesced LDG.128, pass-major (dep distance 7)
        {
            uint4 bb[7];
#pragma unroll
            for (int j = 0; j < 7; j++) bb[j] = bs[j * 32];
#pragma unroll
            for (int j = 0; j < 7; j++) mma16816(acc[j], Ah, bb[j].x, bb[j].y);   // hi*hi
#pragma unroll
            for (int j = 0; j < 7; j++) mma16816(acc[j], Al, bb[j].x, bb[j].y);   // lo*hi
#pragma unroll
            for (int j = 0; j < 7; j++) mma16816(acc[j], Ah, bb[j].z, bb[j].w);   // hi*lo
        }
        // group 2: nt 7..12
        {
            uint4 bb[6];
#pragma unroll
            for (int j = 0; j < 6; j++) bb[j] = bs[(7 + j) * 32];
#pragma unroll
            for (int j = 0; j < 6; j++) mma16816(acc[7 + j], Ah, bb[j].x, bb[j].y);
#pragma unroll
            for (int j = 0; j < 6; j++) mma16816(acc[7 + j], Al, bb[j].x, bb[j].y);
#pragma unroll
            for (int j = 0; j < 6; j++) mma16816(acc[7 + j], Ah, bb[j].z, bb[j].w);
        }
    }

    // epilogue: fragments -> sA in expm layout
    {
        const int rl0 = w * 16 + g;
#pragma unroll
        for (int nt = 0; nt < NT; nt++) {
            int col = nt * 8 + 2 * q;
            if (col < MSZ) {
                *(float2*)(sA + rl0 * EXP_STR + col)       = make_float2(acc[nt][0], acc[nt][1]);
                *(float2*)(sA + (rl0 + 8) * EXP_STR + col) = make_float2(acc[nt][2], acc[nt][3]);
            }
        }
    }
    __syncthreads();   // lie_alg complete in sA

    // ================= expm phase: E = I + A + A^2/2 + A^3/6 + A^3*(A/24 + A^2/120 + A^3/720) =====
    {
        const int m  = tid >> 1;       // local matrix 0..127
        const int h  = tid & 1;
        const int i0 = 5 * h;
        const int mb = m * EXP_STR;

        ull acc2[5][5];
#pragma unroll
        for (int ii = 0; ii < 5; ii++)
#pragma unroll
            for (int jp = 0; jp < 5; jp++) acc2[ii][jp] = 0ull;

        // A^2 (own rows) -> acc2
#pragma unroll
        for (int kp = 0; kp < 5; kp++) {
            const int k0 = 2 * kp, k1 = k0 + 1;
            ull r0[5], r1[5];
#pragma unroll
            for (int jp = 0; jp < 5; jp++) {
                r0[jp] = lds2(sA + mb + k0 * 10 + 2 * jp);
                r1[jp] = lds2(sA + mb + k1 * 10 + 2 * jp);
            }
#pragma unroll
            for (int ii = 0; ii < 5; ii++) {
                float2 za = *(const float2*)(sA + mb + (i0 + ii) * 10 + k0);
                ull z0 = pack2(za.x), z1 = pack2(za.y);
#pragma unroll
                for (int jp = 0; jp < 5; jp++) { fma2(acc2[ii][jp], z0, r0[jp]); fma2(acc2[ii][jp], z1, r1[jp]); }
            }
        }

        // A^3 = A^2 @ A -> sC (two row-groups to bound register pressure)
#pragma unroll
        for (int grp = 0; grp < 2; grp++) {
            const int gbase = grp * 3;
            const int rows  = grp == 0 ? 3 : 2;
            ull a3[3][5];
#pragma unroll
            for (int ii = 0; ii < 3; ii++)
#pragma unroll
                for (int jp = 0; jp < 5; jp++) a3[ii][jp] = 0ull;
#pragma unroll
            for (int kp = 0; kp < 5; kp++) {
                const int k0 = 2 * kp, k1 = k0 + 1;
                ull r0[5], r1[5];
#pragma unroll
                for (int jp = 0; jp < 5; jp++) {
                    r0[jp] = lds2(sA + mb + k0 * 10 + 2 * jp);
                    r1[jp] = lds2(sA + mb + k1 * 10 + 2 * jp);
                }
#pragma unroll
                for (int ii = 0; ii < 3; ii++) {
                    if (ii < rows) {
                        float2 f = unpk(acc2[gbase + ii][kp]);
                        ull z0 = pack2(f.x), z1 = pack2(f.y);
#pragma unroll
                        for (int jp = 0; jp < 5; jp++) { fma2(a3[ii][jp], z0, r0[jp]); fma2(a3[ii][jp], z1, r1[jp]); }
                    }
                }
            }
#pragma unroll
            for (int ii = 0; ii < 3; ii++) {
                if (ii < rows) {
                    const int gi = i0 + gbase + ii;
#pragma unroll
                    for (int jp = 0; jp < 5; jp++)
                        *(float2*)(sC + mb + gi * 10 + 2 * jp) = unpk(a3[ii][jp]);
                }
            }
        }
        __syncthreads();   // all matmul reads of A (sA) complete before W overwrite

        // W = A/24 + A^2/120 + A^3/720 -> sA (own rows); U = I + A + A^2/2 + A^3/6 -> acc2
        {
            const float c2 = 0.5f, c3 = 1.f/6.f, c4 = 1.f/24.f, c5 = 1.f/120.f, c6 = 1.f/720.f;
#pragma unroll
            for (int ii = 0; ii < 5; ii++) {
                const int gi = i0 + ii;
#pragma unroll
                for (int jp = 0; jp < 5; jp++) {
                    float2 a  = *(const float2*)(sA + mb + gi * 10 + 2 * jp);
                    float2 b3 = *(const float2*)(sC + mb + gi * 10 + 2 * jp);
                    float2 b2 = unpk(acc2[ii][jp]);
                    float wx = a.x * c4 + b2.x * c5 + b3.x * c6;
                    float wy = a.y * c4 + b2.y * c5 + b3.y * c6;
                    float ux = (gi == 2 * jp     ? 1.f : 0.f) + a.x + b2.x * c2 + b3.x * c3;
                    float uy = (gi == 2 * jp + 1 ? 1.f : 0.f) + a.y + b2.y * c2 + b3.y * c3;
                    *(float2*)(sA + mb + gi * 10 + 2 * jp) = make_float2(wx, wy);
                    acc2[ii][jp] = pk(ux, uy);
                }
            }
        }
        __syncthreads();   // W complete in sA

        // E = U + A^3 @ W  (A^3 from sC own rows; W rows from sA)
#pragma unroll
        for (int kp = 0; kp < 5; kp++) {
            const int k0 = 2 * kp, k1 = k0 + 1;
            ull r0[5], r1[5];
#pragma unroll
            for (int jp = 0; jp < 5; jp++) {
                r0[jp] = lds2(sA + mb + k0 * 10 + 2 * jp);
                r1[jp] = lds2(sA + mb + k1 * 10 + 2 * jp);
            }
#pragma unroll
            for (int ii = 0; ii < 5; ii++) {
                float2 f = *(const float2*)(sC + mb + (i0 + ii) * 10 + k0);
                ull z0 = pack2(f.x), z1 = pack2(f.y);
#pragma unroll
                for (int jp = 0; jp < 5; jp++) { fma2(acc2[ii][jp], z0, r0[jp]); fma2(acc2[ii][jp], z1, r1[jp]); }
            }
        }

        // store own 5 rows (50 contiguous floats)
        float* op = out + (rowBase + m) * MSZ + i0 * 10;
#pragma unroll
        for (int ii = 0; ii < 5; ii++)
#pragma unroll
            for (int jp = 0; jp < 5; jp++)
                *(float2*)(op + ii * 10 + 2 * jp) = unpk(acc2[ii][jp]);
    }
}

// ---------------- launch ----------------
extern "C" void kernel_launch(void* const* d_in, const int* in_sizes, int n_in,
                              void* d_out, int out_size)
{
    const float* z     = (const float*)d_in[0];   // [B, 512]
    const float* basis = (const float*)d_in[1];   // [512, 10, 10]
    float* out = (float*)d_out;                   // [B, 10, 10]

    int B = in_sizes[0] / ZDIM;                   // 131072

    cudaFuncSetAttribute(lie_fused, cudaFuncAttributeMaxDynamicSharedMemorySize, SMEM_DYN);

    conv_basis<<<52, 256>>>(basis);               // 13312 fragment slots
    lie_fused<<<B / 128, 256, SMEM_DYN>>>(z, out);
}

// round 9
// speedup vs baseline: 2.8937x; 1.1434x over previous
#include <cuda_runtime.h>
#include <cuda_fp16.h>
#include <cstdint>
#include <cstddef>

#define DI __device__ __forceinline__
typedef unsigned long long ull;

static constexpr int ZDIM = 512;
static constexpr int MSZ  = 100;
static constexpr int NT   = 13;                      // n8 tiles (104 >= 100)
static constexpr int TSTEPS = ZDIM / 16;             // 32 k16-tiles
static constexpr int EXP_STR   = 106;                // even (LDS.64 aligned), conflict-free residues
static constexpr int SA_FLOATS = 128 * EXP_STR;      // 13568 floats = 54272 B
static constexpr int SMEM_DYN  = 2 * SA_FLOATS * 4;  // 108544 B (sA + sC)
static constexpr int STAGE_U4  = NT * 32;            // 416 uint4 = 6656 B per k16 stage
static constexpr int NSTAGE    = 4;                  // ring: 26624 B inside sC

// basis fragments, fragment-ordered: [t 0..31][nt 0..12][lane 0..31] = (b0h,b1h,b0l,b1l)
__device__ uint4 g_bfrag[TSTEPS * STAGE_U4];         // 212,992 B

DI void fma2(ull& d, ull a, ull b) { asm("fma.rn.f32x2 %0, %1, %2, %0;" : "+l"(d) : "l"(a), "l"(b)); }
DI ull pack2(float v) { ull r; asm("mov.b64 %0, {%1, %1};" : "=l"(r) : "f"(v)); return r; }
DI ull pk(float x, float y) { ull r; asm("mov.b64 %0, {%1, %2};" : "=l"(r) : "f"(x), "f"(y)); return r; }
DI float2 unpk(ull v) { float2 f; asm("mov.b64 {%0, %1}, %2;" : "=f"(f.x), "=f"(f.y) : "l"(v)); return f; }
DI ull lds2(const float* p) { float2 v = *(const float2*)p; return pk(v.x, v.y); }

DI uint32_t smem_u32(const void* p) {
    uint32_t a;
    asm("{ .reg .u64 t; cvta.to.shared.u64 t, %1; cvt.u32.u64 %0, t; }" : "=r"(a) : "l"(p));
    return a;
}
DI void cpasync16(uint32_t saddr, const void* g) {
    asm volatile("cp.async.cg.shared.global [%0], [%1], 16;" :: "r"(saddr), "l"(g));
}
DI void cpcommit() { asm volatile("cp.async.commit_group;" ::: "memory"); }
DI void cpwait2()  { asm volatile("cp.async.wait_group 2;" ::: "memory"); }
DI void cpwait0()  { asm volatile("cp.async.wait_group 0;" ::: "memory"); }

// split fp32 pair into f16x2 hi + f16x2 residual-lo
DI void cvt_split(float x, float y, uint32_t& hi, uint32_t& lo) {
    __half2 h = __floats2half2_rn(x, y);
    __half2 l = __floats2half2_rn(x - __low2float(h), y - __high2float(h));
    hi = *reinterpret_cast<uint32_t*>(&h);
    lo = *reinterpret_cast<uint32_t*>(&l);
}

DI void mma16816(float* d, const uint32_t* a, uint32_t b0, uint32_t b1) {
    asm volatile("mma.sync.aligned.m16n8k16.row.col.f32.f16.f16.f32 "
        "{%0,%1,%2,%3}, {%4,%5,%6,%7}, {%8,%9}, {%0,%1,%2,%3};"
        : "+f"(d[0]), "+f"(d[1]), "+f"(d[2]), "+f"(d[3])
        : "r"(a[0]), "r"(a[1]), "r"(a[2]), "r"(a[3]), "r"(b0), "r"(b1));
}

// ---------- pre-kernel: convert basis -> fragment-ordered split-fp16 global array ----------
extern "C" __global__ void __launch_bounds__(256)
conv_basis(const float* __restrict__ basis)
{
    int s = blockIdx.x * 256 + threadIdx.x;          // 0 .. 13311
    if (s >= TSTEPS * STAGE_U4) return;
    int t  = s / STAGE_U4;
    int r  = s - t * STAGE_U4;
    int nt = r >> 5;
    int ln = r & 31;
    int qq = ln & 3;
    int n  = nt * 8 + (ln >> 2);
    uint4 val = make_uint4(0u, 0u, 0u, 0u);
    if (n < MSZ) {
        int k0 = t * 16 + 2 * qq;
        float v0 = basis[(size_t)k0 * MSZ + n];
        float v1 = basis[(size_t)(k0 + 1) * MSZ + n];
        float v2 = basis[(size_t)(k0 + 8) * MSZ + n];
        float v3 = basis[(size_t)(k0 + 9) * MSZ + n];
        cvt_split(v0, v1, val.x, val.z);
        cvt_split(v2, v3, val.y, val.w);
    }
    g_bfrag[s] = val;
}

// ---------- fused kernel: GEMM (split-fp16 3-pass mma.sync, cp.async B ring) + expm ----------
extern "C" __global__ void __launch_bounds__(256, 2)
lie_fused(const float* __restrict__ z, float* __restrict__ out)
{
    extern __shared__ float smem[];
    float* sA = smem;                 // lie_alg / W working set
    float* sC = smem + SA_FLOATS;     // GEMM: B ring; expm: A^3 buffer
    const uint32_t ring_base = smem_u32(sC);

    const int tid = threadIdx.x, lane = tid & 31, w = tid >> 5;
    const int g = lane >> 2, q = lane & 3;
    const size_t rowBase = (size_t)blockIdx.x * 128;
    const size_t row0 = rowBase + w * 16 + g;
    const float* zr0 = z + row0 * ZDIM;
    const float* zr1 = zr0 + 8 * ZDIM;

    // ================= GEMM phase =================
    float acc[NT][4];
#pragma unroll
    for (int nt = 0; nt < NT; nt++) { acc[nt][0]=0.f; acc[nt][1]=0.f; acc[nt][2]=0.f; acc[nt][3]=0.f; }

    // cp.async stage issuer: stage s -> ring slot s&3. 416 uint4; threads 0..255 take i, i+256.
    auto issue_stage = [&](int s) {
        const uint4* gsrc = g_bfrag + (size_t)s * STAGE_U4;
        uint32_t sdst = ring_base + (uint32_t)(s & 3) * (STAGE_U4 * 16);
        cpasync16(sdst + tid * 16, gsrc + tid);
        int i2 = tid + 256;
        if (i2 < STAGE_U4) cpasync16(sdst + i2 * 16, gsrc + i2);
    };

    // prologue: 3 stages in flight
    issue_stage(0); cpcommit();
    issue_stage(1); cpcommit();
    issue_stage(2); cpcommit();

    // prefetch first k16-tile of z fragments
    float2 p00, p01, p10, p11;
    {
        const int kb = 2 * q;
        p00 = *(const float2*)(zr0 + kb);  p01 = *(const float2*)(zr0 + kb + 8);
        p10 = *(const float2*)(zr1 + kb);  p11 = *(const float2*)(zr1 + kb + 8);
    }

    for (int t = 0; t < TSTEPS; t++) {
        cpwait2();          // pending <= 2  =>  stage t landed (one commit per iteration)
        __syncthreads();    // cross-thread visibility of stage t; all reads of slot (t-1)&3 done
        if (t + 3 < TSTEPS) issue_stage(t + 3);
        cpcommit();         // commit every iteration (possibly empty) to keep group accounting exact

        uint32_t Ah[4], Al[4];
        cvt_split(p00.x, p00.y, Ah[0], Al[0]);   // (row g,   k lo)
        cvt_split(p10.x, p10.y, Ah[1], Al[1]);   // (row g+8, k lo)
        cvt_split(p01.x, p01.y, Ah[2], Al[2]);   // (row g,   k hi)
        cvt_split(p11.x, p11.y, Ah[3], Al[3]);   // (row g+8, k hi)
        if (t + 1 < TSTEPS) {
            const int kb = (t + 1) * 16 + 2 * q;
            p00 = *(const float2*)(zr0 + kb);  p01 = *(const float2*)(zr0 + kb + 8);
            p10 = *(const float2*)(zr1 + kb);  p11 = *(const float2*)(zr1 + kb + 8);
        }

        const uint4* bs = (const uint4*)sC + (size_t)(t & 3) * STAGE_U4 + lane;

        // group 1: nt 0..6 — LDS.128 conflict-free, pass-major (dep distance 7)
        {
            uint4 bb[7];
#pragma unroll
            for (int j = 0; j < 7; j++) bb[j] = bs[j * 32];
#pragma unroll
            for (int j = 0; j < 7; j++) mma16816(acc[j], Ah, bb[j].x, bb[j].y);   // hi*hi
#pragma unroll
            for (int j = 0; j < 7; j++) mma16816(acc[j], Al, bb[j].x, bb[j].y);   // lo*hi
#pragma unroll
            for (int j = 0; j < 7; j++) mma16816(acc[j], Ah, bb[j].z, bb[j].w);   // hi*lo
        }
        // group 2: nt 7..12
        {
            uint4 bb[6];
#pragma unroll
            for (int j = 0; j < 6; j++) bb[j] = bs[(7 + j) * 32];
#pragma unroll
            for (int j = 0; j < 6; j++) mma16816(acc[7 + j], Ah, bb[j].x, bb[j].y);
#pragma unroll
            for (int j = 0; j < 6; j++) mma16816(acc[7 + j], Al, bb[j].x, bb[j].y);
#pragma unroll
            for (int j = 0; j < 6; j++) mma16816(acc[7 + j], Ah, bb[j].z, bb[j].w);
        }
    }

    // epilogue: fragments -> sA in expm layout
    {
        const int rl0 = w * 16 + g;
#pragma unroll
        for (int nt = 0; nt < NT; nt++) {
            int col = nt * 8 + 2 * q;
            if (col < MSZ) {
                *(float2*)(sA + rl0 * EXP_STR + col)       = make_float2(acc[nt][0], acc[nt][1]);
                *(float2*)(sA + (rl0 + 8) * EXP_STR + col) = make_float2(acc[nt][2], acc[nt][3]);
            }
        }
    }
    cpwait0();           // drain async groups before sC is reused for A^3
    __syncthreads();     // lie_alg complete in sA; ring dead

    // ================= expm phase: E = I + A + A^2/2 + A^3/6 + A^3*(A/24 + A^2/120 + A^3/720) =====
    {
        const int m  = tid >> 1;       // local matrix 0..127
        const int h  = tid & 1;
        const int i0 = 5 * h;
        const int mb = m * EXP_STR;

        ull acc2[5][5];
#pragma unroll
        for (int ii = 0; ii < 5; ii++)
#pragma unroll
            for (int jp = 0; jp < 5; jp++) acc2[ii][jp] = 0ull;

        // A^2 (own rows) -> acc2
#pragma unroll
        for (int kp = 0; kp < 5; kp++) {
            const int k0 = 2 * kp, k1 = k0 + 1;
            ull r0[5], r1[5];
#pragma unroll
            for (int jp = 0; jp < 5; jp++) {
                r0[jp] = lds2(sA + mb + k0 * 10 + 2 * jp);
                r1[jp] = lds2(sA + mb + k1 * 10 + 2 * jp);
            }
#pragma unroll
            for (int ii = 0; ii < 5; ii++) {
                float2 za = *(const float2*)(sA + mb + (i0 + ii) * 10 + k0);
                ull z0 = pack2(za.x), z1 = pack2(za.y);
#pragma unroll
                for (int jp = 0; jp < 5; jp++) { fma2(acc2[ii][jp], z0, r0[jp]); fma2(acc2[ii][jp], z1, r1[jp]); }
            }
        }

        // A^3 = A^2 @ A -> sC (two row-groups to bound register pressure)
#pragma unroll
        for (int grp = 0; grp < 2; grp++) {
            const int gbase = grp * 3;
            const int rows  = grp == 0 ? 3 : 2;
            ull a3[3][5];
#pragma unroll
            for (int ii = 0; ii < 3; ii++)
#pragma unroll
                for (int jp = 0; jp < 5; jp++) a3[ii][jp] = 0ull;
#pragma unroll
            for (int kp = 0; kp < 5; kp++) {
                const int k0 = 2 * kp, k1 = k0 + 1;
                ull r0[5], r1[5];
#pragma unroll
                for (int jp = 0; jp < 5; jp++) {
                    r0[jp] = lds2(sA + mb + k0 * 10 + 2 * jp);
                    r1[jp] = lds2(sA + mb + k1 * 10 + 2 * jp);
                }
#pragma unroll
                for (int ii = 0; ii < 3; ii++) {
                    if (ii < rows) {
                        float2 f = unpk(acc2[gbase + ii][kp]);
                        ull z0 = pack2(f.x), z1 = pack2(f.y);
#pragma unroll
                        for (int jp = 0; jp < 5; jp++) { fma2(a3[ii][jp], z0, r0[jp]); fma2(a3[ii][jp], z1, r1[jp]); }
                    }
                }
            }
#pragma unroll
            for (int ii = 0; ii < 3; ii++) {
                if (ii < rows) {
                    const int gi = i0 + gbase + ii;
#pragma unroll
                    for (int jp = 0; jp < 5; jp++)
                        *(float2*)(sC + mb + gi * 10 + 2 * jp) = unpk(a3[ii][jp]);
                }
            }
        }
        __syncthreads();   // all matmul reads of A (sA) complete before W overwrite

        // W = A/24 + A^2/120 + A^3/720 -> sA (own rows); U = I + A + A^2/2 + A^3/6 -> acc2
        {
            const float c2 = 0.5f, c3 = 1.f/6.f, c4 = 1.f/24.f, c5 = 1.f/120.f, c6 = 1.f/720.f;
#pragma unroll
            for (int ii = 0; ii < 5; ii++) {
                const int gi = i0 + ii;
#pragma unroll
                for (int jp = 0; jp < 5; jp++) {
                    float2 a  = *(const float2*)(sA + mb + gi * 10 + 2 * jp);
                    float2 b3 = *(const float2*)(sC + mb + gi * 10 + 2 * jp);
                    float2 b2 = unpk(acc2[ii][jp]);
                    float wx = a.x * c4 + b2.x * c5 + b3.x * c6;
                    float wy = a.y * c4 + b2.y * c5 + b3.y * c6;
                    float ux = (gi == 2 * jp     ? 1.f : 0.f) + a.x + b2.x * c2 + b3.x * c3;
                    float uy = (gi == 2 * jp + 1 ? 1.f : 0.f) + a.y + b2.y * c2 + b3.y * c3;
                    *(float2*)(sA + mb + gi * 10 + 2 * jp) = make_float2(wx, wy);
                    acc2[ii][jp] = pk(ux, uy);
                }
            }
        }
        __syncthreads();   // W complete in sA

        // E = U + A^3 @ W  (A^3 from sC own rows; W rows from sA)
#pragma unroll
        for (int kp = 0; kp < 5; kp++) {
            const int k0 = 2 * kp, k1 = k0 + 1;
            ull r0[5], r1[5];
#pragma unroll
            for (int jp = 0; jp < 5; jp++) {
                r0[jp] = lds2(sA + mb + k0 * 10 + 2 * jp);
                r1[jp] = lds2(sA + mb + k1 * 10 + 2 * jp);
            }
#pragma unroll
            for (int ii = 0; ii < 5; ii++) {
                float2 f = *(const float2*)(sC + mb + (i0 + ii) * 10 + k0);
                ull z0 = pack2(f.x), z1 = pack2(f.y);
#pragma unroll
                for (int jp = 0; jp < 5; jp++) { fma2(acc2[ii][jp], z0, r0[jp]); fma2(acc2[ii][jp], z1, r1[jp]); }
            }
        }

        // store own 5 rows (50 contiguous floats)
        float* op = out + (rowBase + m) * MSZ + i0 * 10;
#pragma unroll
        for (int ii = 0; ii < 5; ii++)
#pragma unroll
            for (int jp = 0; jp < 5; jp++)
                *(float2*)(op + ii * 10 + 2 * jp) = unpk(acc2[ii][jp]);
    }
}

// ---------------- launch ----------------
extern "C" void kernel_launch(void* const* d_in, const int* in_sizes, int n_in,
                              void* d_out, int out_size)
{
    const float* z     = (const float*)d_in[0];   // [B, 512]
    const float* basis = (const float*)d_in[1];   // [512, 10, 10]
    float* out = (float*)d_out;                   // [B, 10, 10]

    int B = in_sizes[0] / ZDIM;                   // 131072

    cudaFuncSetAttribute(lie_fused, cudaFuncAttributeMaxDynamicSharedMemorySize, SMEM_DYN);

    conv_basis<<<52, 256>>>(basis);               // 13312 fragment slots
    lie_fused<<<B / 128, 256, SMEM_DYN>>>(z, out);
}